// round 15
// baseline (speedup 1.0000x reference)
#include <cuda_runtime.h>
#include <math.h>

// ---------------------------------------------------------------------------
// KANConvNet round 14: R13 baseline (padded a/b/c phi planes, uniform tap
// offset) with L0's 3 K-slices fused into ONE kernel (in-block channel
// chunks, SMEM weight reload, register-resident accumulators) -> no L0
// partial buffers; epilogue becomes maxpool_sum_phi_pad<1>.
// ---------------------------------------------------------------------------

// L0 input (x): 8x3x224x224, pad 3 -> 230x230
#define HP0 230
#define NPAD0 (8 * 3 * HP0 * HP0)
// L1 input (pooled 56x56), pad 1 -> 58x58
#define HP1 58
#define NPAD1 (8 * 16 * HP1 * HP1)
// L2 input (pooled 14x14), pad 1 -> 16x16
#define HP2 16
#define NPAD2 (8 * 32 * HP2 * HP2)

__device__ float g_wp0[147 * 9 * 16];
__device__ float g_wp1[144 * 9 * 32];
__device__ float g_wp2[288 * 9 * 64];
__device__ float g_wpc[64  * 9 * 200];

__device__ float4 g_phi0a[NPAD0];
__device__ float4 g_phi0b[NPAD0];
__device__ float  g_phi0c[NPAD0];
__device__ float  g_a0[8 * 16 * 112 * 112];
__device__ float4 g_phi1a[NPAD1];
__device__ float4 g_phi1b[NPAD1];
__device__ float  g_phi1c[NPAD1];
__device__ float  g_part1[12 * 8 * 32 * 28 * 28];
__device__ float4 g_phi2a[NPAD2];
__device__ float4 g_phi2b[NPAD2];
__device__ float  g_phi2c[NPAD2];
__device__ float  g_part2[36 * 8 * 64 * 7 * 7];
__device__ float  g_a2[8 * 64 * 7 * 7];

#define N0P (147 * 9 * 16)
#define N1P (144 * 9 * 32)
#define N2P (288 * 9 * 64)
#define NCP (64  * 9 * 200)

// ---------------- packed f32x2 helpers ----------------
__device__ __forceinline__ long long pk2(float a) {
    long long r;
    asm("mov.b64 %0, {%1, %1};" : "=l"(r) : "f"(a));
    return r;
}
__device__ __forceinline__ long long ffma2(long long a, long long b, long long c) {
    long long d;
    asm("fma.rn.f32x2 %0, %1, %2, %3;" : "=l"(d) : "l"(a), "l"(b), "l"(c));
    return d;
}
__device__ __forceinline__ float2 upk2(long long a) {
    float x, y;
    asm("mov.b64 {%0, %1}, %2;" : "=f"(x), "=f"(y) : "l"(a));
    return make_float2(x, y);
}

// ---------------- dense 9-coefficient evaluation ----------------
__device__ __forceinline__ void eval9(float x, float* c) {
    float sig = 1.0f / (1.0f + __expf(-x));
    c[0] = x * sig;
    float t  = fmaf(x, 2.5f, 5.5f);          // (x + 2.2) / 0.4
    float mf = floorf(t);
    bool inr = (mf >= 0.0f) && (mf <= 10.0f);
    mf = fminf(fmaxf(mf, 0.0f), 10.0f);
    float u  = t - mf;
    float u2 = u * u;
    float u3 = u2 * u;
    float om = 1.0f - u;
    const float s6 = 1.0f / 6.0f;
    float w0 = s6 * om * om * om;
    float w1 = s6 * fmaf(3.0f, u3, fmaf(-6.0f, u2, 4.0f));
    float w2 = s6 * fmaf(-3.0f, u3, fmaf(3.0f, u2, fmaf(3.0f, u, 1.0f)));
    float w3 = s6 * u3;
    int m = (int)mf;
#pragma unroll
    for (int r = 1; r < 9; r++) {
        int tt = (r - 1) - (m - 3);
        float cv = 0.0f;
        cv = (tt == 0) ? w0 : cv;
        cv = (tt == 1) ? w1 : cv;
        cv = (tt == 2) ? w2 : cv;
        cv = (tt == 3) ? w3 : cv;
        c[r] = inr ? cv : 0.0f;
    }
}

// eval5 (sparse) for the classifier head
__device__ __forceinline__ void eval5(float x, float& c0, float* w, int* r) {
    float sig = 1.0f / (1.0f + __expf(-x));
    c0 = x * sig;
    float t  = fmaf(x, 2.5f, 5.5f);
    float mf = floorf(t);
    bool inr = (mf >= 0.0f) && (mf <= 10.0f);
    mf = fminf(fmaxf(mf, 0.0f), 10.0f);
    float u  = t - mf;
    float u2 = u * u;
    float u3 = u2 * u;
    float om = 1.0f - u;
    const float s6 = 1.0f / 6.0f;
    float a0 = s6 * om * om * om;
    float a1 = s6 * fmaf(3.0f, u3, fmaf(-6.0f, u2, 4.0f));
    float a2 = s6 * fmaf(-3.0f, u3, fmaf(3.0f, u2, fmaf(3.0f, u, 1.0f)));
    float a3 = s6 * u3;
    int m = (int)mf;
    w[0] = (inr && m >= 3)            ? a0 : 0.0f;
    w[1] = (inr && m >= 2 && m <= 9)  ? a1 : 0.0f;
    w[2] = (inr && m >= 1 && m <= 8)  ? a2 : 0.0f;
    w[3] = (inr && m <= 7)            ? a3 : 0.0f;
#pragma unroll
    for (int t4 = 0; t4 < 4; t4++) {
        int j = m - 3 + t4;
        j = j < 0 ? 0 : (j > 7 ? 7 : j);
        r[t4] = 1 + j;
    }
}

__device__ __forceinline__ void store_phi_abc(float4* pa, float4* pb, float* pc,
                                              long long i, const float* c) {
    pa[i] = make_float4(c[0], c[1], c[2], c[3]);
    pb[i] = make_float4(c[4], c[5], c[6], c[7]);
    pc[i] = c[8];
}

// ---------------- phi precompute into PADDED layout (layer-0 input) --------
__global__ void phi_eval_pad(const float* __restrict__ x,
                             float4* __restrict__ pa, float4* __restrict__ pb,
                             float* __restrict__ pc,
                             int B, int C, int H, int W, int P, int npad) {
    int i = blockIdx.x * blockDim.x + threadIdx.x;
    if (i >= npad) return;
    int WP = W + 2 * P, HPd = H + 2 * P;
    int wp_ = i % WP;
    int t   = i / WP;
    int hp_ = t % HPd;
    t /= HPd;
    int c = t % C;
    int b = t / C;
    int hin = hp_ - P, win = wp_ - P;
    float xv = 0.0f;
    if (hin >= 0 && hin < H && win >= 0 && win < W)
        xv = x[((b * C + c) * H + hin) * W + win];
    float cf[9];
    eval9(xv, cf);
    store_phi_abc(pa, pb, pc, i, cf);
}

// ---------------- merged weight packing ----------------
__device__ __forceinline__ void pack_one(int idx,
                                         const float* __restrict__ bw,
                                         const float* __restrict__ sw,
                                         const float* __restrict__ sc,
                                         float* __restrict__ wp,
                                         int OUT, int IN) {
    int i   = idx / (9 * OUT);
    int rem = idx - i * 9 * OUT;
    int r   = rem / OUT;
    int o   = rem - r * OUT;
    int oi  = o * IN + i;
    float v = (r == 0) ? bw[oi] : sw[oi * 8 + (r - 1)] * sc[oi];
    wp[idx] = v;
}

__global__ void pack_all(const float* bw0, const float* sw0, const float* sc0,
                         const float* bw1, const float* sw1, const float* sc1,
                         const float* bw2, const float* sw2, const float* sc2,
                         const float* bwc, const float* swc, const float* scc,
                         float* wp0, float* wp1, float* wp2, float* wpc) {
    int idx = blockIdx.x * blockDim.x + threadIdx.x;
    if (idx < N0P) { pack_one(idx, bw0, sw0, sc0, wp0, 16, 147); return; }
    idx -= N0P;
    if (idx < N1P) { pack_one(idx, bw1, sw1, sc1, wp1, 32, 144); return; }
    idx -= N1P;
    if (idx < N2P) { pack_one(idx, bw2, sw2, sc2, wp2, 64, 288); return; }
    idx -= N2P;
    if (idx < NCP) { pack_one(idx, bwc, swc, scc, wpc, 200, 64); }
}

// ---------------- shared FMA step (16 outputs) ----------------
__device__ __forceinline__ void fmastep16x(const float* wr,
                                           const float4& ca, const float4& cb,
                                           float cc, long long* acc) {
#pragma unroll
    for (int r = 0; r < 9; r++) {
        const ulonglong2* wv = (const ulonglong2*)(wr + r * 16);
        float cf;
        if      (r == 0) cf = ca.x;
        else if (r == 1) cf = ca.y;
        else if (r == 2) cf = ca.z;
        else if (r == 3) cf = ca.w;
        else if (r == 4) cf = cb.x;
        else if (r == 5) cf = cb.y;
        else if (r == 6) cf = cb.z;
        else if (r == 7) cf = cb.w;
        else             cf = cc;
        long long cp = pk2(cf);
#pragma unroll
        for (int q = 0; q < 4; q++) {
            ulonglong2 a = wv[q];
            acc[2 * q]     = ffma2(cp, (long long)a.x, acc[2 * q]);
            acc[2 * q + 1] = ffma2(cp, (long long)a.y, acc[2 * q + 1]);
        }
    }
}

// ---------------------------------------------------------------------------
// L0 fused conv: all 147 taps in one kernel via 3 in-block channel chunks
// (SMEM reload per chunk), relu'd output written directly. PX=2, T=128.
// ---------------------------------------------------------------------------
template <int T, int PX>
__global__ void __launch_bounds__(T, 4)
kan_conv0(const float4* __restrict__ pa, const float4* __restrict__ pb,
          const float* __restrict__ pc,
          const float* __restrict__ wp,    // [147][9][16]
          float* __restrict__ out) {       // (8,16,112,112) relu'd
    __shared__ float swm[49 * 9 * 16];     // 28224 B
    const int K = 7, HPd = HP0, WPd = HP0;

    const int N = 8 * 112 * 112;
    int  off[PX];
    bool pv[PX];
#pragma unroll
    for (int p = 0; p < PX; p++) {
        int gp = blockIdx.x * T * PX + p * T + threadIdx.x;
        pv[p]  = gp < N;
        int g  = pv[p] ? gp : 0;
        int b  = g / (112 * 112);
        int rr = g - b * 112 * 112;
        int ho = rr / 112;
        int wo = rr - ho * 112;
        off[p] = b * 3 * HPd * WPd + (ho * 2) * WPd + wo * 2;
    }

    long long acc[PX][8];
#pragma unroll
    for (int p = 0; p < PX; p++)
#pragma unroll
        for (int k = 0; k < 8; k++) acc[p][k] = 0LL;

#pragma unroll 1
    for (int ch = 0; ch < 3; ch++) {
        __syncthreads();
        for (int idx = threadIdx.x; idx < 49 * 9 * 16; idx += T)
            swm[idx] = wp[ch * 49 * 9 * 16 + idx];
        __syncthreads();

        int kh = 0, kw = 0;
        int uofs = ch * HPd * WPd;
#pragma unroll 1
        for (int fl = 0; fl < 49; fl++) {
            float4 crA[PX], crB[PX];
            float  crC[PX];
#pragma unroll
            for (int p = 0; p < PX; p++) {
                int idx = off[p] + uofs;
                crA[p] = __ldg(pa + idx);
                crB[p] = __ldg(pb + idx);
                crC[p] = __ldg(pc + idx);
            }
            const float* wr = swm + fl * 144;
#pragma unroll
            for (int p = 0; p < PX; p++)
                fmastep16x(wr, crA[p], crB[p], crC[p], acc[p]);

            kw++; uofs++;
            if (kw == K) { kw = 0; kh++; uofs += WPd - K; }
        }
    }

    const long long OHW = 112 * 112;
#pragma unroll
    for (int p = 0; p < PX; p++) {
        if (!pv[p]) continue;
        int gp = blockIdx.x * T * PX + p * T + threadIdx.x;
        int b  = gp / (112 * 112);
        int rr = gp - b * 112 * 112;
        float* op = out + (long long)(b * 16) * OHW + rr;
#pragma unroll
        for (int k = 0; k < 8; k++) {
            float2 v = upk2(acc[p][k]);
            op[(2 * k) * OHW]     = fmaxf(v.x, 0.0f);
            op[(2 * k + 1) * OHW] = fmaxf(v.y, 0.0f);
        }
    }
}

// ---------------------------------------------------------------------------
// Dense gather-GEMM conv over PADDED phi (a/b/c planes) — L1/L2 (unchanged).
// ---------------------------------------------------------------------------
template <int CIN, int K, int S, int OUT, int OT, int PX, int T, int FSL>
__global__ void __launch_bounds__(T, 3)
kan_conv_g(const float4* __restrict__ pa, const float4* __restrict__ pb,
           const float* __restrict__ pc,
           const float* __restrict__ wp,    // [F][9][OUT]
           float* __restrict__ out,
           int B, int HPd, int WPd, int Ho, int Wo) {
    __shared__ float swm[FSL * 9 * OT];
    const int NOT = OUT / OT;
    const int sl  = blockIdx.y / NOT;
    const int ot  = blockIdx.y - sl * NOT;

    for (int idx = threadIdx.x; idx < FSL * 9 * OT; idx += T) {
        int f   = idx / (9 * OT);
        int rem = idx - f * 9 * OT;
        int r   = rem / OT;
        int o   = rem - r * OT;
        swm[idx] = wp[((sl * FSL + f) * 9 + r) * OUT + ot * OT + o];
    }
    __syncthreads();

    const int N = B * Ho * Wo;
    int  off[PX];
    bool pv[PX];
#pragma unroll
    for (int p = 0; p < PX; p++) {
        int gp = blockIdx.x * T * PX + p * T + threadIdx.x;
        pv[p]  = gp < N;
        int g  = pv[p] ? gp : 0;
        int b  = g / (Ho * Wo);
        int rr = g - b * Ho * Wo;
        int ho = rr / Wo;
        int wo = rr - ho * Wo;
        off[p] = b * CIN * HPd * WPd + (ho * S) * WPd + wo * S;
    }

    long long acc[PX][OT / 2];
#pragma unroll
    for (int p = 0; p < PX; p++)
#pragma unroll
        for (int k = 0; k < OT / 2; k++) acc[p][k] = 0LL;

    int f0 = sl * FSL;
    int c  = f0 / (K * K);
    int r0 = f0 - c * K * K;
    int kh = r0 / K;
    int kw = r0 - kh * K;
    int uofs = (c * HPd + kh) * WPd + kw;

#pragma unroll 1
    for (int fl = 0; fl < FSL; fl++) {
        float4 crA[PX], crB[PX];
        float  crC[PX];
#pragma unroll
        for (int p = 0; p < PX; p++) {
            int idx = off[p] + uofs;
            crA[p] = __ldg(pa + idx);
            crB[p] = __ldg(pb + idx);
            crC[p] = __ldg(pc + idx);
        }

        const float* wr = swm + fl * 9 * OT;
#pragma unroll
        for (int p = 0; p < PX; p++)
            fmastep16x(wr, crA[p], crB[p], crC[p], acc[p]);

        kw++; uofs++;
        if (kw == K) {
            kw = 0; kh++; uofs += WPd - K;
            if (kh == K) { kh = 0; c++; uofs += (HPd - K) * WPd; }
        }
    }

    long long HW = (long long)Ho * Wo;
    float* ob = out + (long long)sl * B * OUT * HW;
#pragma unroll
    for (int p = 0; p < PX; p++) {
        if (!pv[p]) continue;
        int gp = blockIdx.x * T * PX + p * T + threadIdx.x;
        int b  = gp / (Ho * Wo);
        int rr = gp - b * Ho * Wo;
        float* op = ob + (long long)(b * OUT + ot * OT) * HW + rr;
#pragma unroll
        for (int k = 0; k < OT / 2; k++) {
            float2 v = upk2(acc[p][k]);
            op[(2 * k) * HW]     = v.x;
            op[(2 * k + 1) * HW] = v.y;
        }
    }
}

// ---------------------------------------------------------------------------
// sum NP partials -> relu -> 2x2 max pool -> phi into PADDED next-layer layout
// (NP=1: plain relu'd input)
// ---------------------------------------------------------------------------
template <int NP>
__global__ void maxpool_sum_phi_pad(const float* __restrict__ in,
                                    float4* __restrict__ pa,
                                    float4* __restrict__ pb,
                                    float* __restrict__ pc,
                                    int B, int C, int H, int W,   // pre-pool dims
                                    int P, int npad) {
    int Ho = H / 2, Wo = W / 2;
    int WP = Wo + 2 * P, HPd = Ho + 2 * P;
    long long sz = (long long)B * C * H * W;
    int i = blockIdx.x * blockDim.x + threadIdx.x;
    if (i >= npad) return;
    int wp_ = i % WP;
    int t   = i / WP;
    int hp_ = t % HPd;
    t /= HPd;
    int c = t % C;
    int b = t / C;
    int ho = hp_ - P, wo = wp_ - P;
    float m = 0.0f;
    if (ho >= 0 && ho < Ho && wo >= 0 && wo < Wo) {
        long long base = ((long long)(b * C + c) * H + ho * 2) * W + wo * 2;
        float v[4] = {0.f, 0.f, 0.f, 0.f};
#pragma unroll
        for (int p = 0; p < NP; p++) {
            const float* ip = in + p * sz + base;
            v[0] += ip[0];
            v[1] += ip[1];
            v[2] += ip[W];
            v[3] += ip[W + 1];
        }
        m = fmaxf(fmaxf(fmaxf(v[0], v[1]), fmaxf(v[2], v[3])), 0.0f);
    }
    float cf[9];
    eval9(m, cf);
    store_phi_abc(pa, pb, pc, i, cf);
}

template <int NP>
__global__ void reduce_relu(const float* __restrict__ in, float* __restrict__ out,
                            int n) {
    int idx = blockIdx.x * blockDim.x + threadIdx.x;
    if (idx >= n) return;
    float s = 0.0f;
#pragma unroll
    for (int p = 0; p < NP; p++) s += in[(long long)p * n + idx];
    out[idx] = fmaxf(s, 0.0f);
}

// ---------------------------------------------------------------------------
// Head: mean(7x7) -> KAN linear 64 -> 200.  8 blocks x 25 outputs.
// ---------------------------------------------------------------------------
__global__ void classifier_kernel(const float* __restrict__ act,
                                  const float* __restrict__ wp,
                                  float* __restrict__ out) {
    __shared__ float mean[512];
    __shared__ float cs[512 * 5];
    __shared__ int   cr[512 * 4];
    int tid = threadIdx.x;
    int ot  = blockIdx.x;

    for (int e = tid; e < 512; e += 256) {
        const float* p = act + e * 49;
        float s = 0.0f;
#pragma unroll
        for (int i = 0; i < 49; i++) s += p[i];
        mean[e] = s * (1.0f / 49.0f);
    }
    __syncthreads();
    for (int e = tid; e < 512; e += 256) {
        float c0, w4[4];
        int   rw[4];
        eval5(mean[e], c0, w4, rw);
        cs[e * 5 + 0] = c0;
#pragma unroll
        for (int t = 0; t < 4; t++) {
            cs[e * 5 + 1 + t] = w4[t];
            cr[e * 4 + t]     = rw[t];
        }
    }
    __syncthreads();
    if (tid < 200) {
        int b = tid / 25;
        int o = ot * 25 + tid % 25;
        float acc = 0.0f;
#pragma unroll 4
        for (int i = 0; i < 64; i++) {
            int e = b * 64 + i;
            const float* cp = &cs[e * 5];
            const int*   rp = &cr[e * 4];
            const float* wr = wp + i * 9 * 200 + o;
            acc = fmaf(cp[0], wr[0], acc);
            acc = fmaf(cp[1], wr[rp[0] * 200], acc);
            acc = fmaf(cp[2], wr[rp[1] * 200], acc);
            acc = fmaf(cp[3], wr[rp[2] * 200], acc);
            acc = fmaf(cp[4], wr[rp[3] * 200], acc);
        }
        out[b * 200 + o] = acc;
    }
}

// ---------------------------------------------------------------------------
// Host launcher
// ---------------------------------------------------------------------------
static void* sym_addr(const void* symbol) {
    void* p = nullptr;
    cudaGetSymbolAddress(&p, symbol);
    return p;
}

extern "C" void kernel_launch(void* const* d_in, const int* in_sizes, int n_in,
                              void* d_out, int out_size) {
    const float* x   = (const float*)d_in[0];
    const float* bw0 = (const float*)d_in[1];
    const float* sw0 = (const float*)d_in[2];
    const float* sc0 = (const float*)d_in[3];
    const float* bw1 = (const float*)d_in[4];
    const float* sw1 = (const float*)d_in[5];
    const float* sc1 = (const float*)d_in[6];
    const float* bw2 = (const float*)d_in[7];
    const float* sw2 = (const float*)d_in[8];
    const float* sc2 = (const float*)d_in[9];
    const float* bwc = (const float*)d_in[10];
    const float* swc = (const float*)d_in[11];
    const float* scc = (const float*)d_in[12];
    float* out = (float*)d_out;

    float*  wp0   = (float*)sym_addr(g_wp0);
    float*  wp1   = (float*)sym_addr(g_wp1);
    float*  wp2   = (float*)sym_addr(g_wp2);
    float*  wpc   = (float*)sym_addr(g_wpc);
    float4* p0a   = (float4*)sym_addr(g_phi0a);
    float4* p0b   = (float4*)sym_addr(g_phi0b);
    float*  p0c   = (float*)sym_addr(g_phi0c);
    float*  a0    = (float*)sym_addr(g_a0);
    float4* p1a   = (float4*)sym_addr(g_phi1a);
    float4* p1b   = (float4*)sym_addr(g_phi1b);
    float*  p1c   = (float*)sym_addr(g_phi1c);
    float*  part1 = (float*)sym_addr(g_part1);
    float4* p2a   = (float4*)sym_addr(g_phi2a);
    float4* p2b   = (float4*)sym_addr(g_phi2b);
    float*  p2c   = (float*)sym_addr(g_phi2c);
    float*  part2 = (float*)sym_addr(g_part2);
    float*  a2    = (float*)sym_addr(g_a2);

    {
        int total = N0P + N1P + N2P + NCP;
        pack_all<<<(total + 255) / 256, 256>>>(bw0, sw0, sc0, bw1, sw1, sc1,
                                               bw2, sw2, sc2, bwc, swc, scc,
                                               wp0, wp1, wp2, wpc);
    }

    // ---- L0: padded phi -> FUSED conv (392 blocks, 16 warps/SM) -> pool+phi ----
    phi_eval_pad<<<(NPAD0 + 255) / 256, 256>>>(x, p0a, p0b, p0c,
                                               8, 3, 224, 224, 3, NPAD0);
    {
        const int T = 128, PX = 2;
        auto k = kan_conv0<T, PX>;
        int grid = (8 * 112 * 112 + T * PX - 1) / (T * PX);   // 392
        k<<<grid, T>>>(p0a, p0b, p0c, wp0, a0);
        maxpool_sum_phi_pad<1><<<(NPAD1 + 255) / 256, 256>>>(a0, p1a, p1b, p1c,
                                                             8, 16, 112, 112, 1, NPAD1);
    }
    // ---- L1: 12 K-slices x 2 o-tiles -> pool+phi(padded) ----
    {
        auto k = kan_conv_g<16, 3, 2, 32, 16, 4, 128, 12>;
        dim3 grid(13, 24);
        k<<<grid, 128>>>(p1a, p1b, p1c, wp1, part1, 8, HP1, HP1, 28, 28);
        maxpool_sum_phi_pad<12><<<(NPAD2 + 255) / 256, 256>>>(part1, p2a, p2b, p2c,
                                                              8, 32, 28, 28, 1, NPAD2);
    }
    // ---- L2: 36 K-slices x 4 o-tiles -> reduce_relu ----
    {
        auto k = kan_conv_g<32, 3, 2, 64, 16, 1, 128, 8>;
        dim3 grid(4, 144);
        k<<<grid, 128>>>(p2a, p2b, p2c, wp2, part2, 8, HP2, HP2, 7, 7);
        reduce_relu<36><<<(8 * 64 * 7 * 7 + 255) / 256, 256>>>(part2, a2, 8 * 64 * 7 * 7);
    }
    classifier_kernel<<<8, 256>>>(a2, wpc, out);

    (void)in_sizes; (void)n_in; (void)out_size;
}

// round 16
// speedup vs baseline: 1.2847x; 1.2847x over previous
#include <cuda_runtime.h>
#include <math.h>

// ---------------------------------------------------------------------------
// KANConvNet round 15: R13 structure (K-sliced gather-GEMM, PX=4, padded phi,
// uniform incremental tap offset) with the 9-coefficient basis reduced to 7:
// all network inputs are >= 0, so spline bases B0 and B1 are identically zero.
//   phi: two float4 planes [silu,B2,B3,B4] and [B5,B6,B7,0]  (2 LDG.128/tap)
//   weights: 7 rows per tap (base + B2..B7)                   (112 FFMA2/tap)
// ---------------------------------------------------------------------------

// L0 input (x): 8x3x224x224, pad 3 -> 230x230
#define HP0 230
#define NPAD0 (8 * 3 * HP0 * HP0)
// L1 input (pooled 56x56), pad 1 -> 58x58
#define HP1 58
#define NPAD1 (8 * 16 * HP1 * HP1)
// L2 input (pooled 14x14), pad 1 -> 16x16
#define HP2 16
#define NPAD2 (8 * 32 * HP2 * HP2)

__device__ float g_wp0[147 * 7 * 16];
__device__ float g_wp1[144 * 7 * 32];
__device__ float g_wp2[288 * 7 * 64];
__device__ float g_wpc[64  * 7 * 200];

__device__ float4 g_phi0a[NPAD0];
__device__ float4 g_phi0b[NPAD0];
__device__ float  g_part0[3 * 8 * 16 * 112 * 112];
__device__ float4 g_phi1a[NPAD1];
__device__ float4 g_phi1b[NPAD1];
__device__ float  g_part1[12 * 8 * 32 * 28 * 28];
__device__ float4 g_phi2a[NPAD2];
__device__ float4 g_phi2b[NPAD2];
__device__ float  g_part2[36 * 8 * 64 * 7 * 7];
__device__ float  g_a2[8 * 64 * 7 * 7];

#define N0P (147 * 7 * 16)
#define N1P (144 * 7 * 32)
#define N2P (288 * 7 * 64)
#define NCP (64  * 7 * 200)

// ---------------- packed f32x2 helpers ----------------
__device__ __forceinline__ long long pk2(float a) {
    long long r;
    asm("mov.b64 %0, {%1, %1};" : "=l"(r) : "f"(a));
    return r;
}
__device__ __forceinline__ long long ffma2(long long a, long long b, long long c) {
    long long d;
    asm("fma.rn.f32x2 %0, %1, %2, %3;" : "=l"(d) : "l"(a), "l"(b), "l"(c));
    return d;
}
__device__ __forceinline__ float2 upk2(long long a) {
    float x, y;
    asm("mov.b64 {%0, %1}, %2;" : "=f"(x), "=f"(y) : "l"(a));
    return make_float2(x, y);
}

// ---------------- 7-coefficient evaluation (valid for x >= 0) --------------
// c[0]=silu(x); c[1..6]=B2..B7. For x>=0: m=floor((x+2.2)/0.4) >= 5, so the
// active basis window j=m-3..m starts at j>=2; slot s=j-2, tt=s-(m-5).
__device__ __forceinline__ void eval7(float x, float* c) {
    float sig = 1.0f / (1.0f + __expf(-x));
    c[0] = x * sig;
    float t  = fmaf(x, 2.5f, 5.5f);
    float mf = floorf(t);
    bool inr = (mf <= 10.0f);
    mf = fminf(mf, 10.0f);
    float u  = t - mf;
    float u2 = u * u;
    float u3 = u2 * u;
    float om = 1.0f - u;
    const float s6 = 1.0f / 6.0f;
    float w0 = s6 * om * om * om;
    float w1 = s6 * fmaf(3.0f, u3, fmaf(-6.0f, u2, 4.0f));
    float w2 = s6 * fmaf(-3.0f, u3, fmaf(3.0f, u2, fmaf(3.0f, u, 1.0f)));
    float w3 = s6 * u3;
    int m5 = (int)mf - 5;       // 0..5
#pragma unroll
    for (int s = 0; s < 6; s++) {
        int tt = s - m5;
        float cv = 0.0f;
        cv = (tt == 0) ? w0 : cv;
        cv = (tt == 1) ? w1 : cv;
        cv = (tt == 2) ? w2 : cv;
        cv = (tt == 3) ? w3 : cv;
        c[1 + s] = inr ? cv : 0.0f;
    }
}

// eval5 (sparse) for the classifier head, 7-row layout (x >= 0).
// Row index = j-1 with j = min(m-3+t, 7) in {2..7} -> rows 1..6.
__device__ __forceinline__ void eval5(float x, float& c0, float* w, int* r) {
    float sig = 1.0f / (1.0f + __expf(-x));
    c0 = x * sig;
    float t  = fmaf(x, 2.5f, 5.5f);
    float mf = floorf(t);
    bool inr = (mf <= 10.0f);
    mf = fminf(mf, 10.0f);
    float u  = t - mf;
    float u2 = u * u;
    float u3 = u2 * u;
    float om = 1.0f - u;
    const float s6 = 1.0f / 6.0f;
    float a0 = s6 * om * om * om;
    float a1 = s6 * fmaf(3.0f, u3, fmaf(-6.0f, u2, 4.0f));
    float a2 = s6 * fmaf(-3.0f, u3, fmaf(3.0f, u2, fmaf(3.0f, u, 1.0f)));
    float a3 = s6 * u3;
    int m = (int)mf;            // 5..10
    w[0] = inr             ? a0 : 0.0f;
    w[1] = (inr && m <= 9) ? a1 : 0.0f;
    w[2] = (inr && m <= 8) ? a2 : 0.0f;
    w[3] = (inr && m <= 7) ? a3 : 0.0f;
#pragma unroll
    for (int t4 = 0; t4 < 4; t4++) {
        int j = m - 3 + t4;
        j = j > 7 ? 7 : j;      // lower bound j>=2 guaranteed
        r[t4] = j - 1;          // rows 1..6
    }
}

__device__ __forceinline__ void store_phi_ab(float4* pa, float4* pb,
                                             long long i, const float* c) {
    pa[i] = make_float4(c[0], c[1], c[2], c[3]);
    pb[i] = make_float4(c[4], c[5], c[6], 0.0f);
}

// ---------------- phi precompute into PADDED layout (layer-0 input) --------
__global__ void phi_eval_pad(const float* __restrict__ x,
                             float4* __restrict__ pa, float4* __restrict__ pb,
                             int B, int C, int H, int W, int P, int npad) {
    int i = blockIdx.x * blockDim.x + threadIdx.x;
    if (i >= npad) return;
    int WP = W + 2 * P, HPd = H + 2 * P;
    int wp_ = i % WP;
    int t   = i / WP;
    int hp_ = t % HPd;
    t /= HPd;
    int c = t % C;
    int b = t / C;
    int hin = hp_ - P, win = wp_ - P;
    float xv = 0.0f;
    if (hin >= 0 && hin < H && win >= 0 && win < W)
        xv = x[((b * C + c) * H + hin) * W + win];
    float cf[7];
    eval7(xv, cf);
    store_phi_ab(pa, pb, i, cf);
}

// ---------------- merged weight packing (7 rows) ----------------
__device__ __forceinline__ void pack_one(int idx,
                                         const float* __restrict__ bw,
                                         const float* __restrict__ sw,
                                         const float* __restrict__ sc,
                                         float* __restrict__ wp,
                                         int OUT, int IN) {
    int i   = idx / (7 * OUT);
    int rem = idx - i * 7 * OUT;
    int r   = rem / OUT;
    int o   = rem - r * OUT;
    int oi  = o * IN + i;
    // row 0: base weight; rows 1..6: spline j = r+1 (j=2..7)
    float v = (r == 0) ? bw[oi] : sw[oi * 8 + (r + 1)] * sc[oi];
    wp[idx] = v;
}

__global__ void pack_all(const float* bw0, const float* sw0, const float* sc0,
                         const float* bw1, const float* sw1, const float* sc1,
                         const float* bw2, const float* sw2, const float* sc2,
                         const float* bwc, const float* swc, const float* scc,
                         float* wp0, float* wp1, float* wp2, float* wpc) {
    int idx = blockIdx.x * blockDim.x + threadIdx.x;
    if (idx < N0P) { pack_one(idx, bw0, sw0, sc0, wp0, 16, 147); return; }
    idx -= N0P;
    if (idx < N1P) { pack_one(idx, bw1, sw1, sc1, wp1, 32, 144); return; }
    idx -= N1P;
    if (idx < N2P) { pack_one(idx, bw2, sw2, sc2, wp2, 64, 288); return; }
    idx -= N2P;
    if (idx < NCP) { pack_one(idx, bwc, swc, scc, wpc, 200, 64); }
}

// ---------------- shared FMA step (16 outputs, 7 rows) ----------------
__device__ __forceinline__ void fmastep16x(const float* wr,
                                           const float4& ca, const float4& cb,
                                           long long* acc) {
#pragma unroll
    for (int r = 0; r < 7; r++) {
        const ulonglong2* wv = (const ulonglong2*)(wr + r * 16);
        float cf;
        if      (r == 0) cf = ca.x;
        else if (r == 1) cf = ca.y;
        else if (r == 2) cf = ca.z;
        else if (r == 3) cf = ca.w;
        else if (r == 4) cf = cb.x;
        else if (r == 5) cf = cb.y;
        else             cf = cb.z;
        long long cp = pk2(cf);
#pragma unroll
        for (int q = 0; q < 4; q++) {
            ulonglong2 a = wv[q];
            acc[2 * q]     = ffma2(cp, (long long)a.x, acc[2 * q]);
            acc[2 * q + 1] = ffma2(cp, (long long)a.y, acc[2 * q + 1]);
        }
    }
}

// ---------------------------------------------------------------------------
// Dense gather-GEMM conv over PADDED phi (a/b planes): no bounds checks.
// ---------------------------------------------------------------------------
template <int CIN, int K, int S, int OUT, int OT, int PX, int T, int FSL>
__global__ void __launch_bounds__(T, 3)
kan_conv_g(const float4* __restrict__ pa, const float4* __restrict__ pb,
           const float* __restrict__ wp,    // [F][7][OUT]
           float* __restrict__ out,
           int B, int HPd, int WPd, int Ho, int Wo) {
    __shared__ float swm[FSL * 7 * OT];
    const int NOT = OUT / OT;
    const int sl  = blockIdx.y / NOT;
    const int ot  = blockIdx.y - sl * NOT;

    for (int idx = threadIdx.x; idx < FSL * 7 * OT; idx += T) {
        int f   = idx / (7 * OT);
        int rem = idx - f * 7 * OT;
        int r   = rem / OT;
        int o   = rem - r * OT;
        swm[idx] = wp[((sl * FSL + f) * 7 + r) * OUT + ot * OT + o];
    }
    __syncthreads();

    const int N = B * Ho * Wo;
    int  off[PX];
    bool pv[PX];
#pragma unroll
    for (int p = 0; p < PX; p++) {
        int gp = blockIdx.x * T * PX + p * T + threadIdx.x;
        pv[p]  = gp < N;
        int g  = pv[p] ? gp : 0;
        int b  = g / (Ho * Wo);
        int rr = g - b * Ho * Wo;
        int ho = rr / Wo;
        int wo = rr - ho * Wo;
        off[p] = b * CIN * HPd * WPd + (ho * S) * WPd + wo * S;
    }

    long long acc[PX][OT / 2];
#pragma unroll
    for (int p = 0; p < PX; p++)
#pragma unroll
        for (int k = 0; k < OT / 2; k++) acc[p][k] = 0LL;

    // block-uniform incremental tap offset
    int f0 = sl * FSL;
    int c  = f0 / (K * K);
    int r0 = f0 - c * K * K;
    int kh = r0 / K;
    int kw = r0 - kh * K;
    int uofs = (c * HPd + kh) * WPd + kw;

#pragma unroll 1
    for (int fl = 0; fl < FSL; fl++) {
        float4 crA[PX], crB[PX];
#pragma unroll
        for (int p = 0; p < PX; p++) {
            int idx = off[p] + uofs;
            crA[p] = __ldg(pa + idx);
            crB[p] = __ldg(pb + idx);
        }

        const float* wr = swm + fl * 7 * OT;
#pragma unroll
        for (int p = 0; p < PX; p++)
            fmastep16x(wr, crA[p], crB[p], acc[p]);

        kw++; uofs++;
        if (kw == K) {
            kw = 0; kh++; uofs += WPd - K;
            if (kh == K) { kh = 0; c++; uofs += (HPd - K) * WPd; }
        }
    }

    long long HW = (long long)Ho * Wo;
    float* ob = out + (long long)sl * B * OUT * HW;
#pragma unroll
    for (int p = 0; p < PX; p++) {
        if (!pv[p]) continue;
        int gp = blockIdx.x * T * PX + p * T + threadIdx.x;
        int b  = gp / (Ho * Wo);
        int rr = gp - b * Ho * Wo;
        float* op = ob + (long long)(b * OUT + ot * OT) * HW + rr;
#pragma unroll
        for (int k = 0; k < OT / 2; k++) {
            float2 v = upk2(acc[p][k]);
            op[(2 * k) * HW]     = v.x;
            op[(2 * k + 1) * HW] = v.y;
        }
    }
}

// ---------------------------------------------------------------------------
// sum NP partials -> relu -> 2x2 max pool -> phi into PADDED next-layer layout
// ---------------------------------------------------------------------------
template <int NP>
__global__ void maxpool_sum_phi_pad(const float* __restrict__ in,
                                    float4* __restrict__ pa,
                                    float4* __restrict__ pb,
                                    int B, int C, int H, int W,   // pre-pool dims
                                    int P, int npad) {
    int Ho = H / 2, Wo = W / 2;
    int WP = Wo + 2 * P, HPd = Ho + 2 * P;
    long long sz = (long long)B * C * H * W;
    int i = blockIdx.x * blockDim.x + threadIdx.x;
    if (i >= npad) return;
    int wp_ = i % WP;
    int t   = i / WP;
    int hp_ = t % HPd;
    t /= HPd;
    int c = t % C;
    int b = t / C;
    int ho = hp_ - P, wo = wp_ - P;
    float m = 0.0f;
    if (ho >= 0 && ho < Ho && wo >= 0 && wo < Wo) {
        long long base = ((long long)(b * C + c) * H + ho * 2) * W + wo * 2;
        float v[4] = {0.f, 0.f, 0.f, 0.f};
#pragma unroll
        for (int p = 0; p < NP; p++) {
            const float* ip = in + p * sz + base;
            v[0] += ip[0];
            v[1] += ip[1];
            v[2] += ip[W];
            v[3] += ip[W + 1];
        }
        m = fmaxf(fmaxf(fmaxf(v[0], v[1]), fmaxf(v[2], v[3])), 0.0f);
    }
    float cf[7];
    eval7(m, cf);
    store_phi_ab(pa, pb, i, cf);
}

template <int NP>
__global__ void reduce_relu(const float* __restrict__ in, float* __restrict__ out,
                            int n) {
    int idx = blockIdx.x * blockDim.x + threadIdx.x;
    if (idx >= n) return;
    float s = 0.0f;
#pragma unroll
    for (int p = 0; p < NP; p++) s += in[(long long)p * n + idx];
    out[idx] = fmaxf(s, 0.0f);
}

// ---------------------------------------------------------------------------
// Head: mean(7x7) -> KAN linear 64 -> 200.  8 blocks x 25 outputs.
// ---------------------------------------------------------------------------
__global__ void classifier_kernel(const float* __restrict__ act,
                                  const float* __restrict__ wp,   // [64][7][200]
                                  float* __restrict__ out) {
    __shared__ float mean[512];
    __shared__ float cs[512 * 5];
    __shared__ int   cr[512 * 4];
    int tid = threadIdx.x;
    int ot  = blockIdx.x;

    for (int e = tid; e < 512; e += 256) {
        const float* p = act + e * 49;
        float s = 0.0f;
#pragma unroll
        for (int i = 0; i < 49; i++) s += p[i];
        mean[e] = s * (1.0f / 49.0f);
    }
    __syncthreads();
    for (int e = tid; e < 512; e += 256) {
        float c0, w4[4];
        int   rw[4];
        eval5(mean[e], c0, w4, rw);
        cs[e * 5 + 0] = c0;
#pragma unroll
        for (int t = 0; t < 4; t++) {
            cs[e * 5 + 1 + t] = w4[t];
            cr[e * 4 + t]     = rw[t];
        }
    }
    __syncthreads();
    if (tid < 200) {
        int b = tid / 25;
        int o = ot * 25 + tid % 25;
        float acc = 0.0f;
#pragma unroll 4
        for (int i = 0; i < 64; i++) {
            int e = b * 64 + i;
            const float* cp = &cs[e * 5];
            const int*   rp = &cr[e * 4];
            const float* wr = wp + i * 7 * 200 + o;
            acc = fmaf(cp[0], wr[0], acc);
            acc = fmaf(cp[1], wr[rp[0] * 200], acc);
            acc = fmaf(cp[2], wr[rp[1] * 200], acc);
            acc = fmaf(cp[3], wr[rp[2] * 200], acc);
            acc = fmaf(cp[4], wr[rp[3] * 200], acc);
        }
        out[b * 200 + o] = acc;
    }
}

// ---------------------------------------------------------------------------
// Host launcher
// ---------------------------------------------------------------------------
static void* sym_addr(const void* symbol) {
    void* p = nullptr;
    cudaGetSymbolAddress(&p, symbol);
    return p;
}

extern "C" void kernel_launch(void* const* d_in, const int* in_sizes, int n_in,
                              void* d_out, int out_size) {
    const float* x   = (const float*)d_in[0];
    const float* bw0 = (const float*)d_in[1];
    const float* sw0 = (const float*)d_in[2];
    const float* sc0 = (const float*)d_in[3];
    const float* bw1 = (const float*)d_in[4];
    const float* sw1 = (const float*)d_in[5];
    const float* sc1 = (const float*)d_in[6];
    const float* bw2 = (const float*)d_in[7];
    const float* sw2 = (const float*)d_in[8];
    const float* sc2 = (const float*)d_in[9];
    const float* bwc = (const float*)d_in[10];
    const float* swc = (const float*)d_in[11];
    const float* scc = (const float*)d_in[12];
    float* out = (float*)d_out;

    float*  wp0   = (float*)sym_addr(g_wp0);
    float*  wp1   = (float*)sym_addr(g_wp1);
    float*  wp2   = (float*)sym_addr(g_wp2);
    float*  wpc   = (float*)sym_addr(g_wpc);
    float4* p0a   = (float4*)sym_addr(g_phi0a);
    float4* p0b   = (float4*)sym_addr(g_phi0b);
    float*  part0 = (float*)sym_addr(g_part0);
    float4* p1a   = (float4*)sym_addr(g_phi1a);
    float4* p1b   = (float4*)sym_addr(g_phi1b);
    float*  part1 = (float*)sym_addr(g_part1);
    float4* p2a   = (float4*)sym_addr(g_phi2a);
    float4* p2b   = (float4*)sym_addr(g_phi2b);
    float*  part2 = (float*)sym_addr(g_part2);
    float*  a2    = (float*)sym_addr(g_a2);

    {
        int total = N0P + N1P + N2P + NCP;
        pack_all<<<(total + 255) / 256, 256>>>(bw0, sw0, sc0, bw1, sw1, sc1,
                                               bw2, sw2, sc2, bwc, swc, scc,
                                               wp0, wp1, wp2, wpc);
    }

    // ---- L0: padded phi -> conv (196x3 blocks, PX=4) -> pool+phi(padded) ----
    phi_eval_pad<<<(NPAD0 + 255) / 256, 256>>>(x, p0a, p0b,
                                               8, 3, 224, 224, 3, NPAD0);
    {
        auto k = kan_conv_g<3, 7, 2, 16, 16, 4, 128, 49>;
        dim3 grid(196, 3);
        k<<<grid, 128>>>(p0a, p0b, wp0, part0, 8, HP0, HP0, 112, 112);
        maxpool_sum_phi_pad<3><<<(NPAD1 + 255) / 256, 256>>>(part0, p1a, p1b,
                                                             8, 16, 112, 112, 1, NPAD1);
    }
    // ---- L1: 12 K-slices x 2 o-tiles -> pool+phi(padded) ----
    {
        auto k = kan_conv_g<16, 3, 2, 32, 16, 4, 128, 12>;
        dim3 grid(13, 24);
        k<<<grid, 128>>>(p1a, p1b, wp1, part1, 8, HP1, HP1, 28, 28);
        maxpool_sum_phi_pad<12><<<(NPAD2 + 255) / 256, 256>>>(part1, p2a, p2b,
                                                              8, 32, 28, 28, 1, NPAD2);
    }
    // ---- L2: 36 K-slices x 4 o-tiles -> reduce_relu ----
    {
        auto k = kan_conv_g<32, 3, 2, 64, 16, 1, 128, 8>;
        dim3 grid(4, 144);
        k<<<grid, 128>>>(p2a, p2b, wp2, part2, 8, HP2, HP2, 7, 7);
        reduce_relu<36><<<(8 * 64 * 7 * 7 + 255) / 256, 256>>>(part2, a2, 8 * 64 * 7 * 7);
    }
    classifier_kernel<<<8, 256>>>(a2, wpc, out);

    (void)in_sizes; (void)n_in; (void)out_size;
}

// round 17
// speedup vs baseline: 1.3060x; 1.0166x over previous
#include <cuda_runtime.h>
#include <math.h>

// ---------------------------------------------------------------------------
// KANConvNet round 16: R15 frozen L0 path; L1/L2 widened to OT=32 (removes
// o-tile LDG duplication); pool epilogues use float2-vectorized reads.
// 7-row basis (inputs >= 0 -> B0,B1 dead), padded a/b phi planes.
// ---------------------------------------------------------------------------

// L0 input (x): 8x3x224x224, pad 3 -> 230x230
#define HP0 230
#define NPAD0 (8 * 3 * HP0 * HP0)
// L1 input (pooled 56x56), pad 1 -> 58x58
#define HP1 58
#define NPAD1 (8 * 16 * HP1 * HP1)
// L2 input (pooled 14x14), pad 1 -> 16x16
#define HP2 16
#define NPAD2 (8 * 32 * HP2 * HP2)

__device__ float g_wp0[147 * 7 * 16];
__device__ float g_wp1[144 * 7 * 32];
__device__ float g_wp2[288 * 7 * 64];
__device__ float g_wpc[64  * 7 * 200];

__device__ float4 g_phi0a[NPAD0];
__device__ float4 g_phi0b[NPAD0];
__device__ float  g_part0[3 * 8 * 16 * 112 * 112];
__device__ float4 g_phi1a[NPAD1];
__device__ float4 g_phi1b[NPAD1];
__device__ float  g_part1[12 * 8 * 32 * 28 * 28];
__device__ float4 g_phi2a[NPAD2];
__device__ float4 g_phi2b[NPAD2];
__device__ float  g_part2[36 * 8 * 64 * 7 * 7];
__device__ float  g_a2[8 * 64 * 7 * 7];

#define N0P (147 * 7 * 16)
#define N1P (144 * 7 * 32)
#define N2P (288 * 7 * 64)
#define NCP (64  * 7 * 200)

// ---------------- packed f32x2 helpers ----------------
__device__ __forceinline__ long long pk2(float a) {
    long long r;
    asm("mov.b64 %0, {%1, %1};" : "=l"(r) : "f"(a));
    return r;
}
__device__ __forceinline__ long long ffma2(long long a, long long b, long long c) {
    long long d;
    asm("fma.rn.f32x2 %0, %1, %2, %3;" : "=l"(d) : "l"(a), "l"(b), "l"(c));
    return d;
}
__device__ __forceinline__ float2 upk2(long long a) {
    float x, y;
    asm("mov.b64 {%0, %1}, %2;" : "=f"(x), "=f"(y) : "l"(a));
    return make_float2(x, y);
}

// ---------------- 7-coefficient evaluation (valid for x >= 0) --------------
__device__ __forceinline__ void eval7(float x, float* c) {
    float sig = 1.0f / (1.0f + __expf(-x));
    c[0] = x * sig;
    float t  = fmaf(x, 2.5f, 5.5f);
    float mf = floorf(t);
    bool inr = (mf <= 10.0f);
    mf = fminf(mf, 10.0f);
    float u  = t - mf;
    float u2 = u * u;
    float u3 = u2 * u;
    float om = 1.0f - u;
    const float s6 = 1.0f / 6.0f;
    float w0 = s6 * om * om * om;
    float w1 = s6 * fmaf(3.0f, u3, fmaf(-6.0f, u2, 4.0f));
    float w2 = s6 * fmaf(-3.0f, u3, fmaf(3.0f, u2, fmaf(3.0f, u, 1.0f)));
    float w3 = s6 * u3;
    int m5 = (int)mf - 5;       // 0..5
#pragma unroll
    for (int s = 0; s < 6; s++) {
        int tt = s - m5;
        float cv = 0.0f;
        cv = (tt == 0) ? w0 : cv;
        cv = (tt == 1) ? w1 : cv;
        cv = (tt == 2) ? w2 : cv;
        cv = (tt == 3) ? w3 : cv;
        c[1 + s] = inr ? cv : 0.0f;
    }
}

// eval5 (sparse) for the classifier head, 7-row layout (x >= 0).
__device__ __forceinline__ void eval5(float x, float& c0, float* w, int* r) {
    float sig = 1.0f / (1.0f + __expf(-x));
    c0 = x * sig;
    float t  = fmaf(x, 2.5f, 5.5f);
    float mf = floorf(t);
    bool inr = (mf <= 10.0f);
    mf = fminf(mf, 10.0f);
    float u  = t - mf;
    float u2 = u * u;
    float u3 = u2 * u;
    float om = 1.0f - u;
    const float s6 = 1.0f / 6.0f;
    float a0 = s6 * om * om * om;
    float a1 = s6 * fmaf(3.0f, u3, fmaf(-6.0f, u2, 4.0f));
    float a2 = s6 * fmaf(-3.0f, u3, fmaf(3.0f, u2, fmaf(3.0f, u, 1.0f)));
    float a3 = s6 * u3;
    int m = (int)mf;            // 5..10
    w[0] = inr             ? a0 : 0.0f;
    w[1] = (inr && m <= 9) ? a1 : 0.0f;
    w[2] = (inr && m <= 8) ? a2 : 0.0f;
    w[3] = (inr && m <= 7) ? a3 : 0.0f;
#pragma unroll
    for (int t4 = 0; t4 < 4; t4++) {
        int j = m - 3 + t4;
        j = j > 7 ? 7 : j;
        r[t4] = j - 1;          // rows 1..6
    }
}

__device__ __forceinline__ void store_phi_ab(float4* pa, float4* pb,
                                             long long i, const float* c) {
    pa[i] = make_float4(c[0], c[1], c[2], c[3]);
    pb[i] = make_float4(c[4], c[5], c[6], 0.0f);
}

// ---------------- phi precompute into PADDED layout (layer-0 input) --------
__global__ void phi_eval_pad(const float* __restrict__ x,
                             float4* __restrict__ pa, float4* __restrict__ pb,
                             int B, int C, int H, int W, int P, int npad) {
    int i = blockIdx.x * blockDim.x + threadIdx.x;
    if (i >= npad) return;
    int WP = W + 2 * P, HPd = H + 2 * P;
    int wp_ = i % WP;
    int t   = i / WP;
    int hp_ = t % HPd;
    t /= HPd;
    int c = t % C;
    int b = t / C;
    int hin = hp_ - P, win = wp_ - P;
    float xv = 0.0f;
    if (hin >= 0 && hin < H && win >= 0 && win < W)
        xv = x[((b * C + c) * H + hin) * W + win];
    float cf[7];
    eval7(xv, cf);
    store_phi_ab(pa, pb, i, cf);
}

// ---------------- merged weight packing (7 rows) ----------------
__device__ __forceinline__ void pack_one(int idx,
                                         const float* __restrict__ bw,
                                         const float* __restrict__ sw,
                                         const float* __restrict__ sc,
                                         float* __restrict__ wp,
                                         int OUT, int IN) {
    int i   = idx / (7 * OUT);
    int rem = idx - i * 7 * OUT;
    int r   = rem / OUT;
    int o   = rem - r * OUT;
    int oi  = o * IN + i;
    float v = (r == 0) ? bw[oi] : sw[oi * 8 + (r + 1)] * sc[oi];
    wp[idx] = v;
}

__global__ void pack_all(const float* bw0, const float* sw0, const float* sc0,
                         const float* bw1, const float* sw1, const float* sc1,
                         const float* bw2, const float* sw2, const float* sc2,
                         const float* bwc, const float* swc, const float* scc,
                         float* wp0, float* wp1, float* wp2, float* wpc) {
    int idx = blockIdx.x * blockDim.x + threadIdx.x;
    if (idx < N0P) { pack_one(idx, bw0, sw0, sc0, wp0, 16, 147); return; }
    idx -= N0P;
    if (idx < N1P) { pack_one(idx, bw1, sw1, sc1, wp1, 32, 144); return; }
    idx -= N1P;
    if (idx < N2P) { pack_one(idx, bw2, sw2, sc2, wp2, 64, 288); return; }
    idx -= N2P;
    if (idx < NCP) { pack_one(idx, bwc, swc, scc, wpc, 200, 64); }
}

// ---------------- shared FMA step (OT outputs, 7 rows) ----------------
template <int OT>
__device__ __forceinline__ void fmastep(const float* wr,
                                        const float4& ca, const float4& cb,
                                        long long* acc) {
#pragma unroll
    for (int r = 0; r < 7; r++) {
        const ulonglong2* wv = (const ulonglong2*)(wr + r * OT);
        float cf;
        if      (r == 0) cf = ca.x;
        else if (r == 1) cf = ca.y;
        else if (r == 2) cf = ca.z;
        else if (r == 3) cf = ca.w;
        else if (r == 4) cf = cb.x;
        else if (r == 5) cf = cb.y;
        else             cf = cb.z;
        long long cp = pk2(cf);
#pragma unroll
        for (int q = 0; q < OT / 4; q++) {
            ulonglong2 a = wv[q];
            acc[2 * q]     = ffma2(cp, (long long)a.x, acc[2 * q]);
            acc[2 * q + 1] = ffma2(cp, (long long)a.y, acc[2 * q + 1]);
        }
    }
}

// ---------------------------------------------------------------------------
// Dense gather-GEMM conv over PADDED phi (a/b planes): no bounds checks.
// ---------------------------------------------------------------------------
template <int CIN, int K, int S, int OUT, int OT, int PX, int T, int FSL>
__global__ void __launch_bounds__(T, 3)
kan_conv_g(const float4* __restrict__ pa, const float4* __restrict__ pb,
           const float* __restrict__ wp,    // [F][7][OUT]
           float* __restrict__ out,
           int B, int HPd, int WPd, int Ho, int Wo) {
    __shared__ float swm[FSL * 7 * OT];
    const int NOT = OUT / OT;
    const int sl  = blockIdx.y / NOT;
    const int ot  = blockIdx.y - sl * NOT;

    for (int idx = threadIdx.x; idx < FSL * 7 * OT; idx += T) {
        int f   = idx / (7 * OT);
        int rem = idx - f * 7 * OT;
        int r   = rem / OT;
        int o   = rem - r * OT;
        swm[idx] = wp[((sl * FSL + f) * 7 + r) * OUT + ot * OT + o];
    }
    __syncthreads();

    const int N = B * Ho * Wo;
    int  off[PX];
    bool pv[PX];
#pragma unroll
    for (int p = 0; p < PX; p++) {
        int gp = blockIdx.x * T * PX + p * T + threadIdx.x;
        pv[p]  = gp < N;
        int g  = pv[p] ? gp : 0;
        int b  = g / (Ho * Wo);
        int rr = g - b * Ho * Wo;
        int ho = rr / Wo;
        int wo = rr - ho * Wo;
        off[p] = b * CIN * HPd * WPd + (ho * S) * WPd + wo * S;
    }

    long long acc[PX][OT / 2];
#pragma unroll
    for (int p = 0; p < PX; p++)
#pragma unroll
        for (int k = 0; k < OT / 2; k++) acc[p][k] = 0LL;

    int f0 = sl * FSL;
    int c  = f0 / (K * K);
    int r0 = f0 - c * K * K;
    int kh = r0 / K;
    int kw = r0 - kh * K;
    int uofs = (c * HPd + kh) * WPd + kw;

#pragma unroll 1
    for (int fl = 0; fl < FSL; fl++) {
        float4 crA[PX], crB[PX];
#pragma unroll
        for (int p = 0; p < PX; p++) {
            int idx = off[p] + uofs;
            crA[p] = __ldg(pa + idx);
            crB[p] = __ldg(pb + idx);
        }

        const float* wr = swm + fl * 7 * OT;
#pragma unroll
        for (int p = 0; p < PX; p++)
            fmastep<OT>(wr, crA[p], crB[p], acc[p]);

        kw++; uofs++;
        if (kw == K) {
            kw = 0; kh++; uofs += WPd - K;
            if (kh == K) { kh = 0; c++; uofs += (HPd - K) * WPd; }
        }
    }

    long long HW = (long long)Ho * Wo;
    float* ob = out + (long long)sl * B * OUT * HW;
#pragma unroll
    for (int p = 0; p < PX; p++) {
        if (!pv[p]) continue;
        int gp = blockIdx.x * T * PX + p * T + threadIdx.x;
        int b  = gp / (Ho * Wo);
        int rr = gp - b * Ho * Wo;
        float* op = ob + (long long)(b * OUT + ot * OT) * HW + rr;
#pragma unroll
        for (int k = 0; k < OT / 2; k++) {
            float2 v = upk2(acc[p][k]);
            op[(2 * k) * HW]     = v.x;
            op[(2 * k + 1) * HW] = v.y;
        }
    }
}

// ---------------------------------------------------------------------------
// sum NP partials -> relu -> 2x2 max pool -> phi into PADDED next-layer layout
// float2-vectorized quad reads.
// ---------------------------------------------------------------------------
template <int NP>
__global__ void maxpool_sum_phi_pad(const float* __restrict__ in,
                                    float4* __restrict__ pa,
                                    float4* __restrict__ pb,
                                    int B, int C, int H, int W,   // pre-pool dims
                                    int P, int npad) {
    int Ho = H / 2, Wo = W / 2;
    int WP = Wo + 2 * P, HPd = Ho + 2 * P;
    long long sz = (long long)B * C * H * W;
    int i = blockIdx.x * blockDim.x + threadIdx.x;
    if (i >= npad) return;
    int wp_ = i % WP;
    int t   = i / WP;
    int hp_ = t % HPd;
    t /= HPd;
    int c = t % C;
    int b = t / C;
    int ho = hp_ - P, wo = wp_ - P;
    float m = 0.0f;
    if (ho >= 0 && ho < Ho && wo >= 0 && wo < Wo) {
        long long base = ((long long)(b * C + c) * H + ho * 2) * W + wo * 2;
        float2 v0 = make_float2(0.f, 0.f), v1 = make_float2(0.f, 0.f);
#pragma unroll
        for (int p = 0; p < NP; p++) {
            const float* ip = in + p * sz + base;
            float2 a = *(const float2*)ip;
            float2 bt = *(const float2*)(ip + W);
            v0.x += a.x;  v0.y += a.y;
            v1.x += bt.x; v1.y += bt.y;
        }
        m = fmaxf(fmaxf(fmaxf(v0.x, v0.y), fmaxf(v1.x, v1.y)), 0.0f);
    }
    float cf[7];
    eval7(m, cf);
    store_phi_ab(pa, pb, i, cf);
}

template <int NP>
__global__ void reduce_relu(const float* __restrict__ in, float* __restrict__ out,
                            int n) {
    int idx = blockIdx.x * blockDim.x + threadIdx.x;
    if (idx >= n) return;
    float s = 0.0f;
#pragma unroll
    for (int p = 0; p < NP; p++) s += in[(long long)p * n + idx];
    out[idx] = fmaxf(s, 0.0f);
}

// ---------------------------------------------------------------------------
// Head: mean(7x7) -> KAN linear 64 -> 200.  8 blocks x 25 outputs.
// ---------------------------------------------------------------------------
__global__ void classifier_kernel(const float* __restrict__ act,
                                  const float* __restrict__ wp,   // [64][7][200]
                                  float* __restrict__ out) {
    __shared__ float mean[512];
    __shared__ float cs[512 * 5];
    __shared__ int   cr[512 * 4];
    int tid = threadIdx.x;
    int ot  = blockIdx.x;

    for (int e = tid; e < 512; e += 256) {
        const float* p = act + e * 49;
        float s = 0.0f;
#pragma unroll
        for (int i = 0; i < 49; i++) s += p[i];
        mean[e] = s * (1.0f / 49.0f);
    }
    __syncthreads();
    for (int e = tid; e < 512; e += 256) {
        float c0, w4[4];
        int   rw[4];
        eval5(mean[e], c0, w4, rw);
        cs[e * 5 + 0] = c0;
#pragma unroll
        for (int t = 0; t < 4; t++) {
            cs[e * 5 + 1 + t] = w4[t];
            cr[e * 4 + t]     = rw[t];
        }
    }
    __syncthreads();
    if (tid < 200) {
        int b = tid / 25;
        int o = ot * 25 + tid % 25;
        float acc = 0.0f;
#pragma unroll 4
        for (int i = 0; i < 64; i++) {
            int e = b * 64 + i;
            const float* cp = &cs[e * 5];
            const int*   rp = &cr[e * 4];
            const float* wr = wp + i * 7 * 200 + o;
            acc = fmaf(cp[0], wr[0], acc);
            acc = fmaf(cp[1], wr[rp[0] * 200], acc);
            acc = fmaf(cp[2], wr[rp[1] * 200], acc);
            acc = fmaf(cp[3], wr[rp[2] * 200], acc);
            acc = fmaf(cp[4], wr[rp[3] * 200], acc);
        }
        out[b * 200 + o] = acc;
    }
}

// ---------------------------------------------------------------------------
// Host launcher
// ---------------------------------------------------------------------------
static void* sym_addr(const void* symbol) {
    void* p = nullptr;
    cudaGetSymbolAddress(&p, symbol);
    return p;
}

extern "C" void kernel_launch(void* const* d_in, const int* in_sizes, int n_in,
                              void* d_out, int out_size) {
    const float* x   = (const float*)d_in[0];
    const float* bw0 = (const float*)d_in[1];
    const float* sw0 = (const float*)d_in[2];
    const float* sc0 = (const float*)d_in[3];
    const float* bw1 = (const float*)d_in[4];
    const float* sw1 = (const float*)d_in[5];
    const float* sc1 = (const float*)d_in[6];
    const float* bw2 = (const float*)d_in[7];
    const float* sw2 = (const float*)d_in[8];
    const float* sc2 = (const float*)d_in[9];
    const float* bwc = (const float*)d_in[10];
    const float* swc = (const float*)d_in[11];
    const float* scc = (const float*)d_in[12];
    float* out = (float*)d_out;

    float*  wp0   = (float*)sym_addr(g_wp0);
    float*  wp1   = (float*)sym_addr(g_wp1);
    float*  wp2   = (float*)sym_addr(g_wp2);
    float*  wpc   = (float*)sym_addr(g_wpc);
    float4* p0a   = (float4*)sym_addr(g_phi0a);
    float4* p0b   = (float4*)sym_addr(g_phi0b);
    float*  part0 = (float*)sym_addr(g_part0);
    float4* p1a   = (float4*)sym_addr(g_phi1a);
    float4* p1b   = (float4*)sym_addr(g_phi1b);
    float*  part1 = (float*)sym_addr(g_part1);
    float4* p2a   = (float4*)sym_addr(g_phi2a);
    float4* p2b   = (float4*)sym_addr(g_phi2b);
    float*  part2 = (float*)sym_addr(g_part2);
    float*  a2    = (float*)sym_addr(g_a2);

    {
        int total = N0P + N1P + N2P + NCP;
        pack_all<<<(total + 255) / 256, 256>>>(bw0, sw0, sc0, bw1, sw1, sc1,
                                               bw2, sw2, sc2, bwc, swc, scc,
                                               wp0, wp1, wp2, wpc);
    }

    // ---- L0 (frozen): padded phi -> conv (196x3, PX=4, OT=16) -> pool+phi ----
    phi_eval_pad<<<(NPAD0 + 255) / 256, 256>>>(x, p0a, p0b,
                                               8, 3, 224, 224, 3, NPAD0);
    {
        auto k = kan_conv_g<3, 7, 2, 16, 16, 4, 128, 49>;
        dim3 grid(196, 3);
        k<<<grid, 128>>>(p0a, p0b, wp0, part0, 8, HP0, HP0, 112, 112);
        maxpool_sum_phi_pad<3><<<(NPAD1 + 255) / 256, 256>>>(part0, p1a, p1b,
                                                             8, 16, 112, 112, 1, NPAD1);
    }
    // ---- L1: OT=32 (1 o-tile), PX=2, 12 K-slices -> pool+phi ----
    {
        auto k = kan_conv_g<16, 3, 2, 32, 32, 2, 128, 12>;
        dim3 grid(25, 12);
        k<<<grid, 128>>>(p1a, p1b, wp1, part1, 8, HP1, HP1, 28, 28);
        maxpool_sum_phi_pad<12><<<(NPAD2 + 255) / 256, 256>>>(part1, p2a, p2b,
                                                              8, 32, 28, 28, 1, NPAD2);
    }
    // ---- L2: OT=32 (2 o-tiles), 36 K-slices -> reduce_relu ----
    {
        auto k = kan_conv_g<32, 3, 2, 64, 32, 1, 128, 8>;
        dim3 grid(4, 72);
        k<<<grid, 128>>>(p2a, p2b, wp2, part2, 8, HP2, HP2, 7, 7);
        reduce_relu<36><<<(8 * 64 * 7 * 7 + 255) / 256, 256>>>(part2, a2, 8 * 64 * 7 * 7);
    }
    classifier_kernel<<<8, 256>>>(a2, wpc, out);

    (void)in_sizes; (void)n_in; (void)out_size;
}